// round 7
// baseline (speedup 1.0000x reference)
#include <cuda_runtime.h>

// out[b,i,d] = x[b,i] * W[i,d] + b[i,d]
// B=128, N=1024, D=512 fp32. Pure HBM-write-bound: 268MB out, 4.5MB in.
//
// R5 = R4 (winning config: grid 8192, B_PER_BLOCK=16, __stcs streaming
// stores) + smem-staged x. R4 front-batched 16 broadcast LDGs per thread
// (MLP_p1=16) -> cross-CTA L1tex-queue contention + 2x CTA tail spread
// (B300_MICROARCH spread model). Now: ONE warp-level LDG per CTA (lanes
// 0-15 fetch the 16 x scalars), LDS broadcast in the loop. L1tex queue is
// left to store wavefronts only.

#define BB 128
#define NN 1024
#define DD 512
#define D4 (DD / 4)          // 128 float4 per row == blockDim
#define B_PER_BLOCK 16

__global__ __launch_bounds__(D4, 8)
void fused_scalar_linear_kernel(const float* __restrict__ x,
                                const float4* __restrict__ W,
                                const float4* __restrict__ bias,
                                float4* __restrict__ out) {
    __shared__ float xs[B_PER_BLOCK];

    const int i  = blockIdx.x;       // neuron row 0..NN-1
    const int bc = blockIdx.y;       // batch chunk 0..BB/B_PER_BLOCK-1
    const int d4 = threadIdx.x;      // 0..D4-1
    const int b0 = bc * B_PER_BLOCK;

    // One LDG instruction for the whole CTA: lanes 0-15 of warp 0 fetch the
    // chunk's x scalars (scattered, stride NN) into smem.
    if (d4 < B_PER_BLOCK) {
        xs[d4] = __ldg(&x[(size_t)(b0 + d4) * NN + i]);
    }

    // One-time register load of this thread's W/b slice.
    const float4 w  = W[i * D4 + d4];
    const float4 bv = bias[i * D4 + d4];

    __syncthreads();

    float4* __restrict__ o_base = out + (size_t)i * D4 + d4;

    #pragma unroll
    for (int k = 0; k < B_PER_BLOCK; ++k) {
        const float xv = xs[k];      // conflict-free LDS broadcast
        float4 o;
        o.x = fmaf(xv, w.x, bv.x);
        o.y = fmaf(xv, w.y, bv.y);
        o.z = fmaf(xv, w.z, bv.z);
        o.w = fmaf(xv, w.w, bv.w);
        // Streaming (evict-first) store: 2KB contiguous per CTA row.
        __stcs(o_base + (size_t)(b0 + k) * (NN * D4), o);
    }
}

extern "C" void kernel_launch(void* const* d_in, const int* in_sizes, int n_in,
                              void* d_out, int out_size) {
    const float*  x    = (const float*)d_in[0];   // [B, N, 1]
    const float4* W    = (const float4*)d_in[1];  // [N, D]
    const float4* bias = (const float4*)d_in[2];  // [N, D]
    float4* out = (float4*)d_out;                 // [B, N, D]

    dim3 grid(NN, BB / B_PER_BLOCK);
    fused_scalar_linear_kernel<<<grid, D4>>>(x, W, bias, out);
}